// round 1
// baseline (speedup 1.0000x reference)
#include <cuda_runtime.h>
#include <math.h>

// ---------------------------------------------------------------------------
// Problem constants
// ---------------------------------------------------------------------------
#define BSZ    256
#define PRIOR  60
#define FRAMES 240
#define POSE   768
#define PRED   180
#define CHUNK  10
#define EPSBN  1e-5f

// ---------------------------------------------------------------------------
// Scratch (static device globals: no allocation anywhere)
// ---------------------------------------------------------------------------
__device__ float g_p1  [BSZ * PRED * POSE];     // conv1 output
__device__ float g_p   [BSZ * PRED * POSE];     // conv2 output (updated in place)
__device__ float g_Wc  [POSE * POSE];           // post_w2 @ post_w1
__device__ float g_bc  [POSE];                  // post_b2 + post_w2 @ post_b1
__device__ float g_Wt  [CHUNK * CHUNK * POSE];  // tmm_w2 @ tmm_w1  [10, 7680]
__device__ float g_bt  [CHUNK];
__device__ float g_hsp [BSZ * POSE];
__device__ float g_mem [BSZ * POSE];
__device__ float g_htm [BSZ * POSE];
__device__ float g_mem2[BSZ * POSE];
__device__ float g_penc[BSZ * CHUNK];
__device__ float g_Mmat[POSE * CHUNK];
__device__ float g_part[16 * 256 * 768];        // split-K partials (covers all uses)

__device__ __forceinline__ float warp_sum(float v) {
    #pragma unroll
    for (int o = 16; o; o >>= 1) v += __shfl_xor_sync(0xffffffffu, v, o);
    return v;
}

// ---------------------------------------------------------------------------
// Generic split-K SGEMM, 128x128x8 tiles, 8x8 per thread, 256 threads.
// C_part[z] = A[bm:, k-slice] * op(B).  BTRANS: B is [N,K] row-major (W^T use).
// ---------------------------------------------------------------------------
template<bool BTRANS>
__global__ __launch_bounds__(256)
void gemm_splitk(const float* __restrict__ A, int lda,
                 const float* __restrict__ B,
                 float* __restrict__ Cp,
                 int M, int N, int K, int kchunk)
{
    __shared__ __align__(16) float As[8][132];
    __shared__ __align__(16) float Bs[8][132];
    const int tid = threadIdx.x;
    const int tx = tid & 15, ty = tid >> 4;
    const int bm = blockIdx.y * 128, bn = blockIdx.x * 128;
    const int k0base = blockIdx.z * kchunk;
    const int kend = min(k0base + kchunk, K);

    float acc[8][8];
    #pragma unroll
    for (int i = 0; i < 8; i++)
        #pragma unroll
        for (int j = 0; j < 8; j++) acc[i][j] = 0.f;

    for (int k0 = k0base; k0 < kend; k0 += 8) {
        #pragma unroll
        for (int i = 0; i < 4; i++) {
            int idx = tid + i * 256;
            int m = idx >> 3, kk = idx & 7;
            int gm = bm + m, gk = k0 + kk;
            As[kk][m] = (gm < M && gk < kend) ? A[(long)gm * lda + gk] : 0.f;
        }
        #pragma unroll
        for (int i = 0; i < 4; i++) {
            int idx = tid + i * 256;
            if (BTRANS) {
                int n = idx >> 3, kk = idx & 7;
                int gn = bn + n, gk = k0 + kk;
                Bs[kk][n] = (gn < N && gk < kend) ? B[(long)gn * K + gk] : 0.f;
            } else {
                int kk = idx >> 7, n = idx & 127;
                int gn = bn + n, gk = k0 + kk;
                Bs[kk][n] = (gn < N && gk < kend) ? B[(long)gk * N + gn] : 0.f;
            }
        }
        __syncthreads();
        #pragma unroll
        for (int kk = 0; kk < 8; kk++) {
            float4 a0 = *(const float4*)&As[kk][ty * 8];
            float4 a1 = *(const float4*)&As[kk][ty * 8 + 4];
            float4 b0 = *(const float4*)&Bs[kk][tx * 8];
            float4 b1 = *(const float4*)&Bs[kk][tx * 8 + 4];
            float a[8] = {a0.x, a0.y, a0.z, a0.w, a1.x, a1.y, a1.z, a1.w};
            float b[8] = {b0.x, b0.y, b0.z, b0.w, b1.x, b1.y, b1.z, b1.w};
            #pragma unroll
            for (int i = 0; i < 8; i++)
                #pragma unroll
                for (int j = 0; j < 8; j++) acc[i][j] = fmaf(a[i], b[j], acc[i][j]);
        }
        __syncthreads();
    }
    float* Cz = Cp + (long)blockIdx.z * M * N;
    #pragma unroll
    for (int i = 0; i < 8; i++) {
        int gm = bm + ty * 8 + i;
        if (gm < M) {
            #pragma unroll
            for (int j = 0; j < 8; j++) {
                int gn = bn + tx * 8 + j;
                if (gn < N) Cz[(long)gm * N + gn] = acc[i][j];
            }
        }
    }
}

__global__ void reduce_splitk(const float* __restrict__ part,
                              const float* __restrict__ bias,
                              float* __restrict__ C, int MN, int N, int S)
{
    int i = blockIdx.x * blockDim.x + threadIdx.x;
    if (i >= MN) return;
    float s = bias ? bias[i % N] : 0.f;
    for (int z = 0; z < S; z++) s += part[(long)z * MN + i];
    C[i] = s;
}

// ---------------------------------------------------------------------------
// Conv1d(k=3,p=1) over pose axis as per-batch GEMM + ReLU + BN(eval) epilogue.
// A = weights [PRED, ICH*3] row-major, B[(i,k), h] = X[b, i, h+k-1].
// ---------------------------------------------------------------------------
__global__ __launch_bounds__(256)
void conv_gemm(const float* __restrict__ X, int ICH,
               const float* __restrict__ W,
               const float* __restrict__ cb,
               const float* __restrict__ bg, const float* __restrict__ bb,
               const float* __restrict__ bmn, const float* __restrict__ bv,
               float* __restrict__ Out)
{
    const int K = ICH * 3;
    const int b = blockIdx.z;
    const float* Xb = X + (long)b * ICH * POSE;
    __shared__ __align__(16) float As[8][132];
    __shared__ __align__(16) float Bs[8][132];
    const int tid = threadIdx.x;
    const int tx = tid & 15, ty = tid >> 4;
    const int bm = blockIdx.y * 128, bn = blockIdx.x * 128;

    float acc[8][8];
    #pragma unroll
    for (int i = 0; i < 8; i++)
        #pragma unroll
        for (int j = 0; j < 8; j++) acc[i][j] = 0.f;

    for (int k0 = 0; k0 < K; k0 += 8) {
        #pragma unroll
        for (int i = 0; i < 4; i++) {
            int idx = tid + i * 256;
            int m = idx >> 3, kk = idx & 7;
            int gm = bm + m, gk = k0 + kk;
            As[kk][m] = (gm < PRED && gk < K) ? W[(long)gm * K + gk] : 0.f;
        }
        #pragma unroll
        for (int i = 0; i < 4; i++) {
            int idx = tid + i * 256;
            int kk = idx >> 7, n = idx & 127;
            int gk = k0 + kk;
            float v = 0.f;
            if (gk < K) {
                int ich = gk / 3;
                int tap = gk - ich * 3;
                int pos = bn + n + tap - 1;
                if (pos >= 0 && pos < POSE) v = Xb[ich * POSE + pos];
            }
            Bs[kk][n] = v;
        }
        __syncthreads();
        #pragma unroll
        for (int kk = 0; kk < 8; kk++) {
            float4 a0 = *(const float4*)&As[kk][ty * 8];
            float4 a1 = *(const float4*)&As[kk][ty * 8 + 4];
            float4 b0 = *(const float4*)&Bs[kk][tx * 8];
            float4 b1 = *(const float4*)&Bs[kk][tx * 8 + 4];
            float a[8] = {a0.x, a0.y, a0.z, a0.w, a1.x, a1.y, a1.z, a1.w};
            float bq[8] = {b0.x, b0.y, b0.z, b0.w, b1.x, b1.y, b1.z, b1.w};
            #pragma unroll
            for (int i = 0; i < 8; i++)
                #pragma unroll
                for (int j = 0; j < 8; j++) acc[i][j] = fmaf(a[i], bq[j], acc[i][j]);
        }
        __syncthreads();
    }
    #pragma unroll
    for (int i = 0; i < 8; i++) {
        int gm = bm + ty * 8 + i;
        if (gm < PRED) {
            float s  = bg[gm] * rsqrtf(bv[gm] + EPSBN);
            float sh = bb[gm] - bmn[gm] * s;
            float cv = cb[gm];
            #pragma unroll
            for (int j = 0; j < 8; j++) {
                int gn = bn + tx * 8 + j;
                float y = fmaxf(acc[i][j] + cv, 0.f);
                Out[((long)b * PRED + gm) * POSE + gn] = y * s + sh;
            }
        }
    }
}

// ---------------------------------------------------------------------------
// Final fused GEMM: out[b,f,:] = concat(x,p)[b,f,:] @ Wc^T + bc
// M = 61440 rows, gathered via per-block row-pointer table.
// ---------------------------------------------------------------------------
__global__ __launch_bounds__(256)
void final_gemm(const float* __restrict__ x, const float* __restrict__ p,
                const float* __restrict__ W, const float* __restrict__ bias,
                float* __restrict__ C)
{
    __shared__ const float* rowp[128];
    __shared__ __align__(16) float As[8][132];
    __shared__ __align__(16) float Bs[8][132];
    const int tid = threadIdx.x;
    const int tx = tid & 15, ty = tid >> 4;
    const int bm = blockIdx.y * 128, bn = blockIdx.x * 128;

    if (tid < 128) {
        int r = bm + tid;
        int bb_ = r / FRAMES;
        int f = r - bb_ * FRAMES;
        rowp[tid] = (f < PRIOR) ? x + ((long)bb_ * PRIOR + f) * POSE
                                : p + ((long)bb_ * PRED + (f - PRIOR)) * POSE;
    }
    __syncthreads();

    float acc[8][8];
    #pragma unroll
    for (int i = 0; i < 8; i++)
        #pragma unroll
        for (int j = 0; j < 8; j++) acc[i][j] = 0.f;

    for (int k0 = 0; k0 < POSE; k0 += 8) {
        #pragma unroll
        for (int i = 0; i < 4; i++) {
            int idx = tid + i * 256;
            int m = idx >> 3, kk = idx & 7;
            As[kk][m] = rowp[m][k0 + kk];
        }
        #pragma unroll
        for (int i = 0; i < 4; i++) {
            int idx = tid + i * 256;
            int n = idx >> 3, kk = idx & 7;
            Bs[kk][n] = W[(long)(bn + n) * POSE + k0 + kk];
        }
        __syncthreads();
        #pragma unroll
        for (int kk = 0; kk < 8; kk++) {
            float4 a0 = *(const float4*)&As[kk][ty * 8];
            float4 a1 = *(const float4*)&As[kk][ty * 8 + 4];
            float4 b0 = *(const float4*)&Bs[kk][tx * 8];
            float4 b1 = *(const float4*)&Bs[kk][tx * 8 + 4];
            float a[8] = {a0.x, a0.y, a0.z, a0.w, a1.x, a1.y, a1.z, a1.w};
            float b[8] = {b0.x, b0.y, b0.z, b0.w, b1.x, b1.y, b1.z, b1.w};
            #pragma unroll
            for (int i = 0; i < 8; i++)
                #pragma unroll
                for (int j = 0; j < 8; j++) acc[i][j] = fmaf(a[i], b[j], acc[i][j]);
        }
        __syncthreads();
    }
    #pragma unroll
    for (int i = 0; i < 8; i++) {
        int gm = bm + ty * 8 + i;
        #pragma unroll
        for (int j = 0; j < 8; j++) {
            int gn = bn + tx * 8 + j;
            C[(long)gm * POSE + gn] = acc[i][j] + bias[gn];
        }
    }
}

// ---------------------------------------------------------------------------
// Small glue kernels
// ---------------------------------------------------------------------------
__global__ void k_bc(const float* __restrict__ w2, const float* __restrict__ b1,
                     const float* __restrict__ b2, float* __restrict__ bc)
{
    int o = blockIdx.x * blockDim.x + threadIdx.x;
    if (o >= POSE) return;
    float s = b2[o];
    for (int m = 0; m < POSE; m++) s += w2[(long)o * POSE + m] * b1[m];
    bc[o] = s;
}

__global__ void k_tmm(const float* __restrict__ w1, const float* __restrict__ b1,
                      const float* __restrict__ w2, const float* __restrict__ b2,
                      float* __restrict__ Wt, float* __restrict__ bt)
{
    int idx = blockIdx.x * blockDim.x + threadIdx.x;
    const int KK = CHUNK * POSE; // 7680
    if (idx < CHUNK * KK) {
        int c = idx / KK, k = idx - c * KK;
        float s = 0.f;
        #pragma unroll
        for (int m = 0; m < CHUNK; m++) s += w2[c * CHUNK + m] * w1[(long)m * KK + k];
        Wt[idx] = s;
    }
    if (idx < CHUNK) {
        float s = b2[idx];
        #pragma unroll
        for (int m = 0; m < CHUNK; m++) s += w2[idx * CHUNK + m] * b1[m];
        bt[idx] = s;
    }
}

// SP gate (in-place on p[:, :CHUNK]) fused with penc = chunk_flat @ Wt^T + bt
__global__ __launch_bounds__(320)
void gate_penc(float* __restrict__ p, const float* __restrict__ mem,
               const float* __restrict__ Wt, const float* __restrict__ bt,
               float* __restrict__ penc)
{
    __shared__ float sm[POSE];
    __shared__ float chunk[CHUNK * POSE];
    __shared__ float sig[CHUNK];
    const int b = blockIdx.x, t = threadIdx.x;
    float* pb = p + (long)b * PRED * POSE;

    for (int i = t; i < POSE; i += 320) sm[i] = mem[(long)b * POSE + i];
    for (int i = t; i < CHUNK * POSE; i += 320) chunk[i] = pb[i];
    __syncthreads();

    const int w = t >> 5, lane = t & 31; // 10 warps, warp w handles chunk index w
    float s = 0.f;
    for (int d = lane; d < POSE; d += 32) s += sm[d] * chunk[w * POSE + d];
    s = warp_sum(s);
    if (lane == 0) sig[w] = 1.f / (1.f + expf(-s));
    __syncthreads();

    for (int i = t; i < CHUNK * POSE; i += 320) {
        int c = i / POSE, d = i - c * POSE;
        float g = sig[c];
        chunk[i] = g * chunk[i] + (1.f - g) * sm[d];
    }
    __syncthreads();
    for (int i = t; i < CHUNK * POSE; i += 320) pb[i] = chunk[i];

    float acc = 0.f;
    for (int k = lane; k < CHUNK * POSE; k += 32) acc += chunk[k] * Wt[(long)w * CHUNK * POSE + k];
    acc = warp_sum(acc);
    if (lane == 0) penc[b * CHUNK + w] = acc + bt[w];
}

// M[d,c] = sum_b mem2[b,d] * penc[b,c]
__global__ void k_M(const float* __restrict__ mem2, const float* __restrict__ penc,
                    float* __restrict__ Mo)
{
    __shared__ float pe[BSZ * CHUNK];
    const int t = threadIdx.x;
    for (int i = t; i < BSZ * CHUNK; i += 256) pe[i] = penc[i];
    __syncthreads();
    int d = blockIdx.x * 256 + t;
    float acc[CHUNK];
    #pragma unroll
    for (int c = 0; c < CHUNK; c++) acc[c] = 0.f;
    for (int b = 0; b < BSZ; b++) {
        float mv = mem2[(long)b * POSE + d];
        #pragma unroll
        for (int c = 0; c < CHUNK; c++) acc[c] = fmaf(mv, pe[b * CHUNK + c], acc[c]);
    }
    #pragma unroll
    for (int c = 0; c < CHUNK; c++) Mo[d * CHUNK + c] = acc[c];
}

// score2 = mem2[b] @ M ; softmax over CHUNK ; p[b,c,:] *= (1 + soft[c])
__global__ __launch_bounds__(320)
void k_score2(float* __restrict__ p, const float* __restrict__ mem2,
              const float* __restrict__ Mo)
{
    __shared__ float sm[POSE];
    __shared__ float sc[CHUNK];
    __shared__ float softs[CHUNK];
    const int b = blockIdx.x, t = threadIdx.x;
    for (int i = t; i < POSE; i += 320) sm[i] = mem2[(long)b * POSE + i];
    __syncthreads();
    const int w = t >> 5, lane = t & 31;
    float s = 0.f;
    for (int d = lane; d < POSE; d += 32) s += sm[d] * Mo[d * CHUNK + w];
    s = warp_sum(s);
    if (lane == 0) sc[w] = s;
    __syncthreads();
    if (t == 0) {
        float mx = sc[0];
        #pragma unroll
        for (int c = 1; c < CHUNK; c++) mx = fmaxf(mx, sc[c]);
        float ssum = 0.f;
        #pragma unroll
        for (int c = 0; c < CHUNK; c++) { float e = expf(sc[c] - mx); softs[c] = e; ssum += e; }
        float inv = 1.f / ssum;
        #pragma unroll
        for (int c = 0; c < CHUNK; c++) softs[c] *= inv;
    }
    __syncthreads();
    float* pb = p + (long)b * PRED * POSE;
    for (int i = t; i < CHUNK * POSE; i += 320) {
        int c = i / POSE;
        pb[i] *= (1.f + softs[c]);
    }
}

// ---------------------------------------------------------------------------
// Launch
// ---------------------------------------------------------------------------
extern "C" void kernel_launch(void* const* d_in, const int* in_sizes, int n_in,
                              void* d_out, int out_size)
{
    const float* x       = (const float*)d_in[0];
    const float* conv1_w = (const float*)d_in[1];
    const float* conv1_b = (const float*)d_in[2];
    const float* bn1_g   = (const float*)d_in[3];
    const float* bn1_b   = (const float*)d_in[4];
    const float* bn1_m   = (const float*)d_in[5];
    const float* bn1_v   = (const float*)d_in[6];
    const float* conv2_w = (const float*)d_in[7];
    const float* conv2_b = (const float*)d_in[8];
    const float* bn2_g   = (const float*)d_in[9];
    const float* bn2_b   = (const float*)d_in[10];
    const float* bn2_m   = (const float*)d_in[11];
    const float* bn2_v   = (const float*)d_in[12];
    const float* sp_w1   = (const float*)d_in[13];
    const float* sp_b1   = (const float*)d_in[14];
    const float* sp_w2   = (const float*)d_in[15];
    const float* sp_b2   = (const float*)d_in[16];
    const float* tmc_w1  = (const float*)d_in[17];
    const float* tmc_b1  = (const float*)d_in[18];
    const float* tmc_w2  = (const float*)d_in[19];
    const float* tmc_b2  = (const float*)d_in[20];
    const float* tmm_w1  = (const float*)d_in[21];
    const float* tmm_b1  = (const float*)d_in[22];
    const float* tmm_w2  = (const float*)d_in[23];
    const float* tmm_b2  = (const float*)d_in[24];
    const float* post_w1 = (const float*)d_in[25];
    const float* post_b1 = (const float*)d_in[26];
    const float* post_w2 = (const float*)d_in[27];
    const float* post_b2 = (const float*)d_in[28];

    float *p1, *p, *Wc, *bc, *Wt, *bt, *hsp, *mem, *htm, *mem2, *penc, *Mm, *part;
    cudaGetSymbolAddress((void**)&p1,   g_p1);
    cudaGetSymbolAddress((void**)&p,    g_p);
    cudaGetSymbolAddress((void**)&Wc,   g_Wc);
    cudaGetSymbolAddress((void**)&bc,   g_bc);
    cudaGetSymbolAddress((void**)&Wt,   g_Wt);
    cudaGetSymbolAddress((void**)&bt,   g_bt);
    cudaGetSymbolAddress((void**)&hsp,  g_hsp);
    cudaGetSymbolAddress((void**)&mem,  g_mem);
    cudaGetSymbolAddress((void**)&htm,  g_htm);
    cudaGetSymbolAddress((void**)&mem2, g_mem2);
    cudaGetSymbolAddress((void**)&penc, g_penc);
    cudaGetSymbolAddress((void**)&Mm,   g_Mmat);
    cudaGetSymbolAddress((void**)&part, g_part);

    // Weight combines (post header collapse, tmm collapse)
    gemm_splitk<false><<<dim3(6, 6, 4), 256>>>(post_w2, POSE, post_w1, part,
                                               POSE, POSE, POSE, 192);
    reduce_splitk<<<(POSE * POSE + 255) / 256, 256>>>(part, nullptr, Wc, POSE * POSE, POSE, 4);
    k_bc<<<3, 256>>>(post_w2, post_b1, post_b2, bc);
    k_tmm<<<300, 256>>>(tmm_w1, tmm_b1, tmm_w2, tmm_b2, Wt, bt);

    // pred_conv
    conv_gemm<<<dim3(6, 2, BSZ), 256>>>(x,  PRIOR, conv1_w, conv1_b, bn1_g, bn1_b, bn1_m, bn1_v, p1);
    conv_gemm<<<dim3(6, 2, BSZ), 256>>>(p1, PRED,  conv2_w, conv2_b, bn2_g, bn2_b, bn2_m, bn2_v, p);

    // tail = x[:, 50:60, :] flattened -> row base x + 50*768, row stride 60*768
    const float* tail = x + (PRIOR - CHUNK) * POSE;
    // SP path
    gemm_splitk<true><<<dim3(6, 2, 16), 256>>>(tail, PRIOR * POSE, sp_w1, part,
                                               BSZ, POSE, CHUNK * POSE, 480);
    reduce_splitk<<<(BSZ * POSE + 255) / 256, 256>>>(part, sp_b1, hsp, BSZ * POSE, POSE, 16);
    gemm_splitk<true><<<dim3(6, 2, 4), 256>>>(hsp, POSE, sp_w2, part,
                                              BSZ, POSE, POSE, 192);
    reduce_splitk<<<(BSZ * POSE + 255) / 256, 256>>>(part, sp_b2, mem, BSZ * POSE, POSE, 4);
    // TMC path
    gemm_splitk<true><<<dim3(6, 2, 16), 256>>>(tail, PRIOR * POSE, tmc_w1, part,
                                               BSZ, POSE, CHUNK * POSE, 480);
    reduce_splitk<<<(BSZ * POSE + 255) / 256, 256>>>(part, tmc_b1, htm, BSZ * POSE, POSE, 16);
    gemm_splitk<true><<<dim3(6, 2, 4), 256>>>(htm, POSE, tmc_w2, part,
                                              BSZ, POSE, POSE, 192);
    reduce_splitk<<<(BSZ * POSE + 255) / 256, 256>>>(part, tmc_b2, mem2, BSZ * POSE, POSE, 4);

    // Memory nets
    gate_penc<<<BSZ, 320>>>(p, mem, Wt, bt, penc);
    k_M<<<3, 256>>>(mem2, penc, Mm);
    k_score2<<<BSZ, 320>>>(p, mem2, Mm);

    // Final collapsed post-header GEMM -> d_out
    final_gemm<<<dim3(6, 480), 256>>>(x, p, Wc, bc, (float*)d_out);
}

// round 2
// speedup vs baseline: 4.6251x; 4.6251x over previous
#include <cuda_runtime.h>
#include <math.h>

// ---------------------------------------------------------------------------
// Problem constants
// ---------------------------------------------------------------------------
#define BSZ    256
#define PRIOR  60
#define FRAMES 240
#define POSE   768
#define PRED   180
#define CHUNK  10
#define EPSBN  1e-5f

// ---------------------------------------------------------------------------
// Scratch (static device globals: no allocation anywhere)
// ---------------------------------------------------------------------------
__device__ float g_p1  [BSZ * PRED * POSE];
__device__ float g_p   [BSZ * PRED * POSE];
__device__ float g_Wc  [POSE * POSE];
__device__ float g_bc  [POSE];
__device__ float g_Wt  [CHUNK * CHUNK * POSE];
__device__ float g_bt  [CHUNK];
__device__ float g_hsp [BSZ * POSE];
__device__ float g_mem [BSZ * POSE];
__device__ float g_htm [BSZ * POSE];
__device__ float g_mem2[BSZ * POSE];
__device__ float g_penc[BSZ * CHUNK];
__device__ float g_Mmat[POSE * CHUNK];
__device__ float g_part[16 * 256 * 768];

__device__ __forceinline__ float warp_sum(float v) {
    #pragma unroll
    for (int o = 16; o; o >>= 1) v += __shfl_xor_sync(0xffffffffu, v, o);
    return v;
}

__device__ __forceinline__ unsigned f2tf(float x) {
    unsigned u;
    asm("cvt.rna.tf32.f32 %0, %1;" : "=r"(u) : "f"(x));
    return u;
}
__device__ __forceinline__ uint4 cvt4(float4 v) {
    return make_uint4(f2tf(v.x), f2tf(v.y), f2tf(v.z), f2tf(v.w));
}

// m16n8k8 tf32 mma on a 128x128 CTA tile, BK=16, warp tile 64x32 (8 warps).
// As[m][k] / Bs[n][k], row stride 20 floats (conflict-free frag LDS + aligned STS.128)
__device__ __forceinline__ void mma_block(const unsigned (*As)[20], const unsigned (*Bs)[20],
                                          float acc[4][4][4],
                                          int warp_row, int warp_col, int gid, int tig)
{
    #pragma unroll
    for (int ks = 0; ks < 16; ks += 8) {
        unsigned a[4][4], bf[4][2];
        #pragma unroll
        for (int mt = 0; mt < 4; mt++) {
            int m0 = warp_row * 64 + mt * 16 + gid;
            a[mt][0] = As[m0][ks + tig];
            a[mt][1] = As[m0 + 8][ks + tig];
            a[mt][2] = As[m0][ks + tig + 4];
            a[mt][3] = As[m0 + 8][ks + tig + 4];
        }
        #pragma unroll
        for (int nt = 0; nt < 4; nt++) {
            int n0 = warp_col * 32 + nt * 8 + gid;
            bf[nt][0] = Bs[n0][ks + tig];
            bf[nt][1] = Bs[n0][ks + tig + 4];
        }
        #pragma unroll
        for (int mt = 0; mt < 4; mt++)
            #pragma unroll
            for (int nt = 0; nt < 4; nt++)
                asm volatile(
                    "mma.sync.aligned.m16n8k8.row.col.f32.tf32.tf32.f32 "
                    "{%0,%1,%2,%3},{%4,%5,%6,%7},{%8,%9},{%0,%1,%2,%3};"
                    : "+f"(acc[mt][nt][0]), "+f"(acc[mt][nt][1]),
                      "+f"(acc[mt][nt][2]), "+f"(acc[mt][nt][3])
                    : "r"(a[mt][0]), "r"(a[mt][1]), "r"(a[mt][2]), "r"(a[mt][3]),
                      "r"(bf[nt][0]), "r"(bf[nt][1]));
    }
}

// ---------------------------------------------------------------------------
// Generic tf32 GEMM, B transposed ([N,K] row-major), split-K partials out.
// ---------------------------------------------------------------------------
__global__ __launch_bounds__(256)
void tf32_gemm_bt(const float* __restrict__ A, long lda,
                  const float* __restrict__ B, long ldb,
                  float* __restrict__ Cpart,
                  int M, int N, int K, int kchunk)
{
    __shared__ __align__(16) unsigned As[2][128][20];
    __shared__ __align__(16) unsigned Bs[2][128][20];
    const int tid = threadIdx.x;
    const int warpid = tid >> 5, lane = tid & 31;
    const int warp_row = warpid >> 2, warp_col = warpid & 3;
    const int gid = lane >> 2, tig = lane & 3;
    const int bm = blockIdx.y * 128, bn = blockIdx.x * 128;
    const int k0base = blockIdx.z * kchunk;
    const int kend = min(k0base + kchunk, K);
    const int nk = (kend - k0base + 15) >> 4;

    float acc[4][4][4];
    #pragma unroll
    for (int mt = 0; mt < 4; mt++)
        #pragma unroll
        for (int nt = 0; nt < 4; nt++)
            #pragma unroll
            for (int r = 0; r < 4; r++) acc[mt][nt][r] = 0.f;

    float4 va[2], vb[2];
    auto loadA = [&](int k0) {
        #pragma unroll
        for (int i = 0; i < 2; i++) {
            int f = tid + i * 256, m = f >> 2, kq = f & 3;
            int gm = bm + m, gk = k0 + kq * 4;
            va[i] = make_float4(0.f, 0.f, 0.f, 0.f);
            if (gm < M && gk < kend) va[i] = *(const float4*)(A + (long)gm * lda + gk);
        }
    };
    auto loadB = [&](int k0) {
        #pragma unroll
        for (int i = 0; i < 2; i++) {
            int f = tid + i * 256, n = f >> 2, kq = f & 3;
            int gn = bn + n, gk = k0 + kq * 4;
            vb[i] = make_float4(0.f, 0.f, 0.f, 0.f);
            if (gn < N && gk < kend) vb[i] = *(const float4*)(B + (long)gn * ldb + gk);
        }
    };
    auto store = [&](int buf) {
        #pragma unroll
        for (int i = 0; i < 2; i++) {
            int f = tid + i * 256, m = f >> 2, kq = f & 3;
            *(uint4*)&As[buf][m][kq * 4] = cvt4(va[i]);
            *(uint4*)&Bs[buf][m][kq * 4] = cvt4(vb[i]);
        }
    };

    loadA(k0base); loadB(k0base); store(0);
    __syncthreads();
    for (int i = 0; i < nk; i++) {
        if (i + 1 < nk) { loadA(k0base + (i + 1) * 16); loadB(k0base + (i + 1) * 16); }
        mma_block(As[i & 1], Bs[i & 1], acc, warp_row, warp_col, gid, tig);
        if (i + 1 < nk) {
            __syncthreads();
            store((i + 1) & 1);
            __syncthreads();
        }
    }

    float* Cz = Cpart + (long)blockIdx.z * M * N;
    #pragma unroll
    for (int mt = 0; mt < 4; mt++) {
        int gm0 = bm + warp_row * 64 + mt * 16 + gid;
        #pragma unroll
        for (int nt = 0; nt < 4; nt++) {
            int gn0 = bn + warp_col * 32 + nt * 8 + tig * 2;
            if (gm0 < M) {
                Cz[(long)gm0 * N + gn0]     = acc[mt][nt][0];
                Cz[(long)gm0 * N + gn0 + 1] = acc[mt][nt][1];
            }
            if (gm0 + 8 < M) {
                Cz[(long)(gm0 + 8) * N + gn0]     = acc[mt][nt][2];
                Cz[(long)(gm0 + 8) * N + gn0 + 1] = acc[mt][nt][3];
            }
        }
    }
}

__global__ void reduce_splitk(const float* __restrict__ part,
                              const float* __restrict__ bias,
                              float* __restrict__ C, int MN, int N, int S)
{
    int i = blockIdx.x * blockDim.x + threadIdx.x;
    if (i >= MN) return;
    float s = bias ? bias[i % N] : 0.f;
    for (int z = 0; z < S; z++) s += part[(long)z * MN + i];
    C[i] = s;
}

// ---------------------------------------------------------------------------
// tf32 conv (k=3, pad=1 over pose axis) + ReLU + BN(eval) epilogue, per batch.
// ---------------------------------------------------------------------------
__global__ __launch_bounds__(256)
void conv_tf32(const float* __restrict__ X, int ICH,
               const float* __restrict__ W,
               const float* __restrict__ cb,
               const float* __restrict__ bg, const float* __restrict__ bb,
               const float* __restrict__ bmn, const float* __restrict__ bv,
               float* __restrict__ Out)
{
    __shared__ __align__(16) unsigned As[2][128][20];
    __shared__ __align__(16) unsigned Bs[2][128][20];
    const int K = ICH * 3;
    const int b = blockIdx.z;
    const float* Xb = X + (long)b * ICH * POSE;
    const int tid = threadIdx.x;
    const int warpid = tid >> 5, lane = tid & 31;
    const int warp_row = warpid >> 2, warp_col = warpid & 3;
    const int gid = lane >> 2, tig = lane & 3;
    const int bm = blockIdx.y * 128, bn = blockIdx.x * 128;
    const int nk = (K + 15) >> 4;

    float acc[4][4][4];
    #pragma unroll
    for (int mt = 0; mt < 4; mt++)
        #pragma unroll
        for (int nt = 0; nt < 4; nt++)
            #pragma unroll
            for (int r = 0; r < 4; r++) acc[mt][nt][r] = 0.f;

    float4 va[2];
    float  vbv[2][4];
    auto loadA = [&](int k0) {
        #pragma unroll
        for (int i = 0; i < 2; i++) {
            int f = tid + i * 256, m = f >> 2, kq = f & 3;
            int gm = bm + m, gk = k0 + kq * 4;
            va[i] = make_float4(0.f, 0.f, 0.f, 0.f);
            if (gm < PRED && gk < K) va[i] = *(const float4*)(W + (long)gm * K + gk);
        }
    };
    // B[(ich,tap)][pos] = Xb[ich][pos+tap-1]; thread holds (n fixed, 4 consecutive k)
    auto loadB = [&](int k0) {
        #pragma unroll
        for (int i = 0; i < 2; i++) {
            int f = tid + i * 256;          // [0,512)
            int nn = f & 127, kg = f >> 7;  // kg in [0,4)
            #pragma unroll
            for (int j = 0; j < 4; j++) {
                int gk = k0 + kg * 4 + j;
                float v = 0.f;
                if (gk < K) {
                    int ich = gk / 3, tap = gk - ich * 3;
                    int pos = bn + nn + tap - 1;
                    if (pos >= 0 && pos < POSE) v = Xb[(long)ich * POSE + pos];
                }
                vbv[i][j] = v;
            }
        }
    };
    auto store = [&](int buf) {
        #pragma unroll
        for (int i = 0; i < 2; i++) {
            int f = tid + i * 256, m = f >> 2, kq = f & 3;
            *(uint4*)&As[buf][m][kq * 4] = cvt4(va[i]);
            int nn = f & 127, kg = f >> 7;
            *(uint4*)&Bs[buf][nn][kg * 4] =
                make_uint4(f2tf(vbv[i][0]), f2tf(vbv[i][1]), f2tf(vbv[i][2]), f2tf(vbv[i][3]));
        }
    };

    loadA(0); loadB(0); store(0);
    __syncthreads();
    for (int i = 0; i < nk; i++) {
        if (i + 1 < nk) { loadA((i + 1) * 16); loadB((i + 1) * 16); }
        mma_block(As[i & 1], Bs[i & 1], acc, warp_row, warp_col, gid, tig);
        if (i + 1 < nk) {
            __syncthreads();
            store((i + 1) & 1);
            __syncthreads();
        }
    }

    #pragma unroll
    for (int mt = 0; mt < 4; mt++) {
        int gm0 = bm + warp_row * 64 + mt * 16 + gid;
        #pragma unroll
        for (int half = 0; half < 2; half++) {
            int gm = gm0 + half * 8;
            if (gm < PRED) {
                float s  = bg[gm] * rsqrtf(bv[gm] + EPSBN);
                float sh = bb[gm] - bmn[gm] * s;
                float cv = cb[gm];
                #pragma unroll
                for (int nt = 0; nt < 4; nt++) {
                    int gn0 = bn + warp_col * 32 + nt * 8 + tig * 2;
                    float y0 = fmaxf(acc[mt][nt][half * 2]     + cv, 0.f);
                    float y1 = fmaxf(acc[mt][nt][half * 2 + 1] + cv, 0.f);
                    Out[((long)b * PRED + gm) * POSE + gn0]     = y0 * s + sh;
                    Out[((long)b * PRED + gm) * POSE + gn0 + 1] = y1 * s + sh;
                }
            }
        }
    }
}

// ---------------------------------------------------------------------------
// Final fused GEMM: out = concat(x,p) @ Wc^T + bc, tf32, row-gather A.
// ---------------------------------------------------------------------------
__global__ __launch_bounds__(256)
void final_tf32(const float* __restrict__ x, const float* __restrict__ p,
                const float* __restrict__ Wm, const float* __restrict__ bias,
                float* __restrict__ C)
{
    __shared__ __align__(16) unsigned As[2][128][20];
    __shared__ __align__(16) unsigned Bs[2][128][20];
    __shared__ const float* rowp[128];
    const int tid = threadIdx.x;
    const int warpid = tid >> 5, lane = tid & 31;
    const int warp_row = warpid >> 2, warp_col = warpid & 3;
    const int gid = lane >> 2, tig = lane & 3;
    const int bm = blockIdx.y * 128, bn = blockIdx.x * 128;
    const int nk = POSE / 16;  // 48

    if (tid < 128) {
        int r = bm + tid;
        int bb_ = r / FRAMES;
        int f = r - bb_ * FRAMES;
        rowp[tid] = (f < PRIOR) ? x + ((long)bb_ * PRIOR + f) * POSE
                                : p + ((long)bb_ * PRED + (f - PRIOR)) * POSE;
    }
    __syncthreads();

    float acc[4][4][4];
    #pragma unroll
    for (int mt = 0; mt < 4; mt++)
        #pragma unroll
        for (int nt = 0; nt < 4; nt++)
            #pragma unroll
            for (int r = 0; r < 4; r++) acc[mt][nt][r] = 0.f;

    float4 va[2], vb[2];
    auto loadAB = [&](int k0) {
        #pragma unroll
        for (int i = 0; i < 2; i++) {
            int f = tid + i * 256, m = f >> 2, kq = f & 3;
            va[i] = *(const float4*)(rowp[m] + k0 + kq * 4);
            vb[i] = *(const float4*)(Wm + (long)(bn + m) * POSE + k0 + kq * 4);
        }
    };
    auto store = [&](int buf) {
        #pragma unroll
        for (int i = 0; i < 2; i++) {
            int f = tid + i * 256, m = f >> 2, kq = f & 3;
            *(uint4*)&As[buf][m][kq * 4] = cvt4(va[i]);
            *(uint4*)&Bs[buf][m][kq * 4] = cvt4(vb[i]);
        }
    };

    loadAB(0); store(0);
    __syncthreads();
    for (int i = 0; i < nk; i++) {
        if (i + 1 < nk) loadAB((i + 1) * 16);
        mma_block(As[i & 1], Bs[i & 1], acc, warp_row, warp_col, gid, tig);
        if (i + 1 < nk) {
            __syncthreads();
            store((i + 1) & 1);
            __syncthreads();
        }
    }

    #pragma unroll
    for (int mt = 0; mt < 4; mt++) {
        int gm0 = bm + warp_row * 64 + mt * 16 + gid;
        #pragma unroll
        for (int nt = 0; nt < 4; nt++) {
            int gn0 = bn + warp_col * 32 + nt * 8 + tig * 2;
            float b0 = bias[gn0], b1 = bias[gn0 + 1];
            C[(long)gm0 * POSE + gn0]           = acc[mt][nt][0] + b0;
            C[(long)gm0 * POSE + gn0 + 1]       = acc[mt][nt][1] + b1;
            C[(long)(gm0 + 8) * POSE + gn0]     = acc[mt][nt][2] + b0;
            C[(long)(gm0 + 8) * POSE + gn0 + 1] = acc[mt][nt][3] + b1;
        }
    }
}

// ---------------------------------------------------------------------------
// fp32 split-K SGEMM (kept for the Wc weight-combine: full fp32 weights)
// ---------------------------------------------------------------------------
__global__ __launch_bounds__(256)
void gemm_splitk_f32(const float* __restrict__ A, int lda,
                     const float* __restrict__ B,
                     float* __restrict__ Cp,
                     int M, int N, int K, int kchunk)
{
    __shared__ __align__(16) float As[8][132];
    __shared__ __align__(16) float Bs[8][132];
    const int tid = threadIdx.x;
    const int tx = tid & 15, ty = tid >> 4;
    const int bm = blockIdx.y * 128, bn = blockIdx.x * 128;
    const int k0base = blockIdx.z * kchunk;
    const int kend = min(k0base + kchunk, K);

    float acc[8][8];
    #pragma unroll
    for (int i = 0; i < 8; i++)
        #pragma unroll
        for (int j = 0; j < 8; j++) acc[i][j] = 0.f;

    for (int k0 = k0base; k0 < kend; k0 += 8) {
        #pragma unroll
        for (int i = 0; i < 4; i++) {
            int idx = tid + i * 256;
            int m = idx >> 3, kk = idx & 7;
            int gm = bm + m, gk = k0 + kk;
            As[kk][m] = (gm < M && gk < kend) ? A[(long)gm * lda + gk] : 0.f;
        }
        #pragma unroll
        for (int i = 0; i < 4; i++) {
            int idx = tid + i * 256;
            int kk = idx >> 7, n = idx & 127;
            int gn = bn + n, gk = k0 + kk;
            Bs[kk][n] = (gn < N && gk < kend) ? B[(long)gk * N + gn] : 0.f;
        }
        __syncthreads();
        #pragma unroll
        for (int kk = 0; kk < 8; kk++) {
            float4 a0 = *(const float4*)&As[kk][ty * 8];
            float4 a1 = *(const float4*)&As[kk][ty * 8 + 4];
            float4 b0 = *(const float4*)&Bs[kk][tx * 8];
            float4 b1 = *(const float4*)&Bs[kk][tx * 8 + 4];
            float a[8] = {a0.x, a0.y, a0.z, a0.w, a1.x, a1.y, a1.z, a1.w};
            float b[8] = {b0.x, b0.y, b0.z, b0.w, b1.x, b1.y, b1.z, b1.w};
            #pragma unroll
            for (int i = 0; i < 8; i++)
                #pragma unroll
                for (int j = 0; j < 8; j++) acc[i][j] = fmaf(a[i], b[j], acc[i][j]);
        }
        __syncthreads();
    }
    float* Cz = Cp + (long)blockIdx.z * M * N;
    #pragma unroll
    for (int i = 0; i < 8; i++) {
        int gm = bm + ty * 8 + i;
        if (gm < M) {
            #pragma unroll
            for (int j = 0; j < 8; j++) {
                int gn = bn + tx * 8 + j;
                if (gn < N) Cz[(long)gm * N + gn] = acc[i][j];
            }
        }
    }
}

// ---------------------------------------------------------------------------
// Small glue kernels (fp32)
// ---------------------------------------------------------------------------
__global__ void k_bc(const float* __restrict__ w2, const float* __restrict__ b1,
                     const float* __restrict__ b2, float* __restrict__ bc)
{
    int o = blockIdx.x * blockDim.x + threadIdx.x;
    if (o >= POSE) return;
    float s = b2[o];
    for (int m = 0; m < POSE; m++) s += w2[(long)o * POSE + m] * b1[m];
    bc[o] = s;
}

__global__ void k_tmm(const float* __restrict__ w1, const float* __restrict__ b1,
                      const float* __restrict__ w2, const float* __restrict__ b2,
                      float* __restrict__ Wt, float* __restrict__ bt)
{
    int idx = blockIdx.x * blockDim.x + threadIdx.x;
    const int KK = CHUNK * POSE;
    if (idx < CHUNK * KK) {
        int c = idx / KK, k = idx - c * KK;
        float s = 0.f;
        #pragma unroll
        for (int m = 0; m < CHUNK; m++) s += w2[c * CHUNK + m] * w1[(long)m * KK + k];
        Wt[idx] = s;
    }
    if (idx < CHUNK) {
        float s = b2[idx];
        #pragma unroll
        for (int m = 0; m < CHUNK; m++) s += w2[idx * CHUNK + m] * b1[m];
        bt[idx] = s;
    }
}

__global__ __launch_bounds__(320)
void gate_penc(float* __restrict__ p, const float* __restrict__ mem,
               const float* __restrict__ Wt, const float* __restrict__ bt,
               float* __restrict__ penc)
{
    __shared__ float sm[POSE];
    __shared__ float chunk[CHUNK * POSE];
    __shared__ float sig[CHUNK];
    const int b = blockIdx.x, t = threadIdx.x;
    float* pb = p + (long)b * PRED * POSE;

    for (int i = t; i < POSE; i += 320) sm[i] = mem[(long)b * POSE + i];
    for (int i = t; i < CHUNK * POSE; i += 320) chunk[i] = pb[i];
    __syncthreads();

    const int w = t >> 5, lane = t & 31;
    float s = 0.f;
    for (int d = lane; d < POSE; d += 32) s += sm[d] * chunk[w * POSE + d];
    s = warp_sum(s);
    if (lane == 0) sig[w] = 1.f / (1.f + expf(-s));
    __syncthreads();

    for (int i = t; i < CHUNK * POSE; i += 320) {
        int c = i / POSE, d = i - c * POSE;
        float g = sig[c];
        chunk[i] = g * chunk[i] + (1.f - g) * sm[d];
    }
    __syncthreads();
    for (int i = t; i < CHUNK * POSE; i += 320) pb[i] = chunk[i];

    float acc = 0.f;
    for (int k = lane; k < CHUNK * POSE; k += 32) acc += chunk[k] * Wt[(long)w * CHUNK * POSE + k];
    acc = warp_sum(acc);
    if (lane == 0) penc[b * CHUNK + w] = acc + bt[w];
}

__global__ void k_M(const float* __restrict__ mem2, const float* __restrict__ penc,
                    float* __restrict__ Mo)
{
    __shared__ float pe[BSZ * CHUNK];
    const int t = threadIdx.x;
    for (int i = t; i < BSZ * CHUNK; i += 256) pe[i] = penc[i];
    __syncthreads();
    int d = blockIdx.x * 256 + t;
    float acc[CHUNK];
    #pragma unroll
    for (int c = 0; c < CHUNK; c++) acc[c] = 0.f;
    for (int b = 0; b < BSZ; b++) {
        float mv = mem2[(long)b * POSE + d];
        #pragma unroll
        for (int c = 0; c < CHUNK; c++) acc[c] = fmaf(mv, pe[b * CHUNK + c], acc[c]);
    }
    #pragma unroll
    for (int c = 0; c < CHUNK; c++) Mo[d * CHUNK + c] = acc[c];
}

__global__ __launch_bounds__(320)
void k_score2(float* __restrict__ p, const float* __restrict__ mem2,
              const float* __restrict__ Mo)
{
    __shared__ float sm[POSE];
    __shared__ float sc[CHUNK];
    __shared__ float softs[CHUNK];
    const int b = blockIdx.x, t = threadIdx.x;
    for (int i = t; i < POSE; i += 320) sm[i] = mem2[(long)b * POSE + i];
    __syncthreads();
    const int w = t >> 5, lane = t & 31;
    float s = 0.f;
    for (int d = lane; d < POSE; d += 32) s += sm[d] * Mo[d * CHUNK + w];
    s = warp_sum(s);
    if (lane == 0) sc[w] = s;
    __syncthreads();
    if (t == 0) {
        float mx = sc[0];
        #pragma unroll
        for (int c = 1; c < CHUNK; c++) mx = fmaxf(mx, sc[c]);
        float ssum = 0.f;
        #pragma unroll
        for (int c = 0; c < CHUNK; c++) { float e = expf(sc[c] - mx); softs[c] = e; ssum += e; }
        float inv = 1.f / ssum;
        #pragma unroll
        for (int c = 0; c < CHUNK; c++) softs[c] *= inv;
    }
    __syncthreads();
    float* pb = p + (long)b * PRED * POSE;
    for (int i = t; i < CHUNK * POSE; i += 320) {
        int c = i / POSE;
        pb[i] *= (1.f + softs[c]);
    }
}

// ---------------------------------------------------------------------------
// Launch
// ---------------------------------------------------------------------------
extern "C" void kernel_launch(void* const* d_in, const int* in_sizes, int n_in,
                              void* d_out, int out_size)
{
    const float* x       = (const float*)d_in[0];
    const float* conv1_w = (const float*)d_in[1];
    const float* conv1_b = (const float*)d_in[2];
    const float* bn1_g   = (const float*)d_in[3];
    const float* bn1_b   = (const float*)d_in[4];
    const float* bn1_m   = (const float*)d_in[5];
    const float* bn1_v   = (const float*)d_in[6];
    const float* conv2_w = (const float*)d_in[7];
    const float* conv2_b = (const float*)d_in[8];
    const float* bn2_g   = (const float*)d_in[9];
    const float* bn2_b   = (const float*)d_in[10];
    const float* bn2_m   = (const float*)d_in[11];
    const float* bn2_v   = (const float*)d_in[12];
    const float* sp_w1   = (const float*)d_in[13];
    const float* sp_b1   = (const float*)d_in[14];
    const float* sp_w2   = (const float*)d_in[15];
    const float* sp_b2   = (const float*)d_in[16];
    const float* tmc_w1  = (const float*)d_in[17];
    const float* tmc_b1  = (const float*)d_in[18];
    const float* tmc_w2  = (const float*)d_in[19];
    const float* tmc_b2  = (const float*)d_in[20];
    const float* tmm_w1  = (const float*)d_in[21];
    const float* tmm_b1  = (const float*)d_in[22];
    const float* tmm_w2  = (const float*)d_in[23];
    const float* tmm_b2  = (const float*)d_in[24];
    const float* post_w1 = (const float*)d_in[25];
    const float* post_b1 = (const float*)d_in[26];
    const float* post_w2 = (const float*)d_in[27];
    const float* post_b2 = (const float*)d_in[28];

    float *p1, *p, *Wc, *bc, *Wt, *bt, *hsp, *mem, *htm, *mem2, *penc, *Mm, *part;
    cudaGetSymbolAddress((void**)&p1,   g_p1);
    cudaGetSymbolAddress((void**)&p,    g_p);
    cudaGetSymbolAddress((void**)&Wc,   g_Wc);
    cudaGetSymbolAddress((void**)&bc,   g_bc);
    cudaGetSymbolAddress((void**)&Wt,   g_Wt);
    cudaGetSymbolAddress((void**)&bt,   g_bt);
    cudaGetSymbolAddress((void**)&hsp,  g_hsp);
    cudaGetSymbolAddress((void**)&mem,  g_mem);
    cudaGetSymbolAddress((void**)&htm,  g_htm);
    cudaGetSymbolAddress((void**)&mem2, g_mem2);
    cudaGetSymbolAddress((void**)&penc, g_penc);
    cudaGetSymbolAddress((void**)&Mm,   g_Mmat);
    cudaGetSymbolAddress((void**)&part, g_part);

    // Weight combines: Wc = post_w2 @ post_w1 (fp32 to keep weight precision)
    gemm_splitk_f32<<<dim3(6, 6, 4), 256>>>(post_w2, POSE, post_w1, part,
                                            POSE, POSE, POSE, 192);
    reduce_splitk<<<(POSE * POSE + 255) / 256, 256>>>(part, nullptr, Wc, POSE * POSE, POSE, 4);
    k_bc<<<3, 256>>>(post_w2, post_b1, post_b2, bc);
    k_tmm<<<300, 256>>>(tmm_w1, tmm_b1, tmm_w2, tmm_b2, Wt, bt);

    // pred_conv (tf32)
    conv_tf32<<<dim3(6, 2, BSZ), 256>>>(x,  PRIOR, conv1_w, conv1_b, bn1_g, bn1_b, bn1_m, bn1_v, p1);
    conv_tf32<<<dim3(6, 2, BSZ), 256>>>(p1, PRED,  conv2_w, conv2_b, bn2_g, bn2_b, bn2_m, bn2_v, p);

    // tail = x[:, 50:60, :] flattened: base x + 50*768, row stride 60*768
    const float* tail = x + (PRIOR - CHUNK) * POSE;
    // SP path (tf32 + split-K)
    tf32_gemm_bt<<<dim3(6, 2, 16), 256>>>(tail, (long)PRIOR * POSE, sp_w1, (long)CHUNK * POSE,
                                          part, BSZ, POSE, CHUNK * POSE, 480);
    reduce_splitk<<<(BSZ * POSE + 255) / 256, 256>>>(part, sp_b1, hsp, BSZ * POSE, POSE, 16);
    tf32_gemm_bt<<<dim3(6, 2, 4), 256>>>(hsp, POSE, sp_w2, POSE,
                                         part, BSZ, POSE, POSE, 192);
    reduce_splitk<<<(BSZ * POSE + 255) / 256, 256>>>(part, sp_b2, mem, BSZ * POSE, POSE, 4);
    // TMC path
    tf32_gemm_bt<<<dim3(6, 2, 16), 256>>>(tail, (long)PRIOR * POSE, tmc_w1, (long)CHUNK * POSE,
                                          part, BSZ, POSE, CHUNK * POSE, 480);
    reduce_splitk<<<(BSZ * POSE + 255) / 256, 256>>>(part, tmc_b1, htm, BSZ * POSE, POSE, 16);
    tf32_gemm_bt<<<dim3(6, 2, 4), 256>>>(htm, POSE, tmc_w2, POSE,
                                         part, BSZ, POSE, POSE, 192);
    reduce_splitk<<<(BSZ * POSE + 255) / 256, 256>>>(part, tmc_b2, mem2, BSZ * POSE, POSE, 4);

    // Memory nets
    gate_penc<<<BSZ, 320>>>(p, mem, Wt, bt, penc);
    k_M<<<3, 256>>>(mem2, penc, Mm);
    k_score2<<<BSZ, 320>>>(p, mem2, Mm);

    // Final collapsed post-header GEMM -> d_out (tf32)
    final_tf32<<<dim3(6, 480), 256>>>(x, p, Wc, bc, (float*)d_out);
}